// round 4
// baseline (speedup 1.0000x reference)
#include <cuda_runtime.h>
#include <cuda_fp16.h>
#include <math.h>

#define N_ROWS_MAX 100000
#define D 64
#define NGH 16
#define NSC 10
#define EPSF 1e-10f
#define FULL 0xFFFFFFFFu

#define RPW 8          // rows per warp
#define WPB 8          // warps per block
#define RPB (RPW*WPB)  // rows per block = 64

// Scratch — device globals per allocation rules.
__device__ float   g_rs_raw[(size_t)N_ROWS_MAX * D];    // raw row_sum (fp32, self reads)
__device__ __half2 g_rs_h[(size_t)N_ROWS_MAX * 32];     // rs/(||rs||^2+eps) fp16
__device__ __half2 g_ce_h[(size_t)N_ROWS_MAX * 32];     // cate_emb fp16 shadow
__device__ float2  g_ss[N_ROWS_MAX];                    // (inv = 1/(sq+eps), selfsim)
__device__ float4  g_W4[64 * 32];                       // [c][d] = W[d][4c..4c+3]

// ---------------------------------------------------------------------------
// Kernel A: per-row scene sums; stores raw fp32 + scaled fp16; (inv,selfsim);
// also transposes W and converts cate_emb to fp16.
// ---------------------------------------------------------------------------
__global__ void rowsum_kernel(const float* __restrict__ scene_emb,
                              const int* __restrict__ cate_scene_pad,
                              const float* __restrict__ agg_W,
                              const float* __restrict__ cate_emb,
                              int n_rows, int v_cates) {
    int gtid = blockIdx.x * blockDim.x + threadIdx.x;
    int nthreads = gridDim.x * blockDim.x;

    // W transpose: first 2048 threads, one float4 each.
    if (gtid < 64 * 32) {
        int d = gtid & 63;
        int c = gtid >> 6;
        g_W4[c * 64 + d] = ((const float4*)agg_W)[d * 32 + c];
    }

    // cate_emb fp32 -> fp16 shadow (grid-stride; v_cates*16 float4 chunks)
    const float4* ce4 = (const float4*)cate_emb;
    for (int t = gtid; t < v_cates * 16; t += nthreads) {
        float4 v = ce4[t];
        __half2 h0 = __floats2half2_rn(v.x, v.y);
        __half2 h1 = __floats2half2_rn(v.z, v.w);
        uint2 u;
        u.x = *reinterpret_cast<unsigned int*>(&h0);
        u.y = *reinterpret_cast<unsigned int*>(&h1);
        ((uint2*)g_ce_h)[t] = u;
    }

    int row = gtid >> 4;
    int sub = gtid & 15;
    if (row >= n_rows) return;
    int lane = threadIdx.x & 31;
    int group_base = lane & 16;

    int myidx = 0;
    if (sub < NSC) myidx = __ldg(cate_scene_pad + (size_t)row * NSC + sub);

    float4 acc = make_float4(0.f, 0.f, 0.f, 0.f);
#pragma unroll
    for (int k = 0; k < NSC; k++) {
        int j = __shfl_sync(FULL, myidx, group_base + k);
        float4 v = ((const float4*)(scene_emb + (size_t)j * D))[sub];
        acc.x += v.x; acc.y += v.y; acc.z += v.z; acc.w += v.w;
    }

    float sq = acc.x * acc.x + acc.y * acc.y + acc.z * acc.z + acc.w * acc.w;
#pragma unroll
    for (int o = 8; o >= 1; o >>= 1)
        sq += __shfl_xor_sync(FULL, sq, o);

    float inv = 1.0f / (sq + EPSF);

    // raw fp32
    ((float4*)(g_rs_raw + (size_t)row * D))[sub] = acc;
    // scaled fp16
    __half2 h0 = __floats2half2_rn(acc.x * inv, acc.y * inv);
    __half2 h1 = __floats2half2_rn(acc.z * inv, acc.w * inv);
    uint2 u;
    u.x = *reinterpret_cast<unsigned int*>(&h0);
    u.y = *reinterpret_cast<unsigned int*>(&h1);
    ((uint2*)g_rs_h)[(size_t)row * 16 + sub] = u;

    if (sub == 0) g_ss[row] = make_float2(inv, sq * inv * inv);
}

// Butterfly merge: combine two lane-distributed partial sums at xor-offset o.
__device__ __forceinline__ float bmerge(float a, float b, int o, int lane) {
    float x = (lane & o) ? b : a;
    float y = (lane & o) ? a : b;
    y = __shfl_xor_sync(FULL, y, o);
    return x + y;
}

// ---------------------------------------------------------------------------
// Kernel B: one warp owns 8 rows. fp16 gathers for neighbors; fp32 self.
// ---------------------------------------------------------------------------
__global__ void __launch_bounds__(256, 4)
main_kernel(const int* __restrict__ c_cate_pad,
            const float* __restrict__ agg_b,
            float* __restrict__ out,
            int n_rows, int v_cates) {
    __shared__ float sH[WPB][RPW * 128];

    int tid  = threadIdx.x;
    int warp = tid >> 5;
    int lane = tid & 31;

    int rowbase = blockIdx.x * RPB + warp * RPW;
    float* sHw = sH[warp];

    // ---- Phase 1: attention per row ----
#pragma unroll 1
    for (int r = 0; r < RPW; r++) {
        int row = rowbase + r;
        if (row >= n_rows) break;

        int nidx = 0;
        if (lane < NGH) nidx = __ldg(c_cate_pad + (size_t)row * NGH + lane);

        float2 a_raw = *(const float2*)(g_rs_raw + (size_t)row * D + 2 * lane);
        float2 ss = g_ss[row];                  // (inv, selfsim)
        float2 a_hat = make_float2(a_raw.x * ss.x, a_raw.y * ss.x);

        // 16 neighbor dot partials (fp16 gathers, 1 wavefront each)
        float dtp[16];
#pragma unroll
        for (int j = 0; j < 16; j++) {
            int p = __shfl_sync(FULL, nidx, j);
            float2 rv = __half22float2(__ldg(g_rs_h + (size_t)p * 32 + lane));
            dtp[j] = fmaf(rv.x, a_hat.x, rv.y * a_hat.y);
        }

        // Butterfly merge tree: lane L ends with full dot for j = L>>1
#pragma unroll
        for (int i = 0; i < 8; i++) dtp[i] = bmerge(dtp[i], dtp[i + 8], 16, lane);
#pragma unroll
        for (int i = 0; i < 4; i++) dtp[i] = bmerge(dtp[i], dtp[i + 4],  8, lane);
#pragma unroll
        for (int i = 0; i < 2; i++) dtp[i] = bmerge(dtp[i], dtp[i + 2],  4, lane);
        dtp[0] = bmerge(dtp[0], dtp[1], 2, lane);
        dtp[0] += __shfl_xor_sync(FULL, dtp[0], 1);

        // miu_j at lanes 2j, 2j+1
        int jj = lane >> 1;
        int pj = __shfl_sync(FULL, nidx, jj);
        float miu = (pj < v_cates - 1) ? __expf(dtp[0]) : 0.f;

        // denom across distinct j
        float dv = (lane & 1) ? 0.f : miu;
#pragma unroll
        for (int o = 16; o >= 1; o >>= 1)
            dv += __shfl_xor_sync(FULL, dv, o);

        float miu_self = (row < v_cates - 1) ? __expf(ss.y) : 0.f;
        float rden = 1.0f / (dv + miu_self + EPSF);

        // aggregation: self + 16 neighbors (fp16 ce gathers)
        float2 c0 = __half22float2(__ldg(g_ce_h + (size_t)row * 32 + lane));
        float ax = miu_self * c0.x;
        float ay = miu_self * c0.y;
#pragma unroll
        for (int j = 0; j < 16; j++) {
            float m = __shfl_sync(FULL, miu, 2 * j);
            int   p = __shfl_sync(FULL, nidx, j);
            float2 cv = __half22float2(__ldg(g_ce_h + (size_t)p * 32 + lane));
            ax = fmaf(m, cv.x, ax);
            ay = fmaf(m, cv.y, ay);
        }

        float2* hh = (float2*)(sHw + r * 128);
        hh[lane]      = a_raw;                              // exact row_sum
        hh[32 + lane] = make_float2(ax * rden, ay * rden);  // agg
    }
    __syncwarp();

    // ---- Phase 2: register-tiled matvec, 8 rows x 2 cols/lane ----
    float acc0[RPW], acc1[RPW];
#pragma unroll
    for (int r = 0; r < RPW; r++) { acc0[r] = 0.f; acc1[r] = 0.f; }

#pragma unroll 4
    for (int c = 0; c < 32; c++) {
        float4 w0 = __ldg(g_W4 + c * 64 + lane);
        float4 w1 = __ldg(g_W4 + c * 64 + 32 + lane);
#pragma unroll
        for (int r = 0; r < RPW; r++) {
            float4 h4 = *(const float4*)(sHw + r * 128 + 4 * c);
            acc0[r] = fmaf(w0.x, h4.x, fmaf(w0.y, h4.y,
                      fmaf(w0.z, h4.z, fmaf(w0.w, h4.w, acc0[r]))));
            acc1[r] = fmaf(w1.x, h4.x, fmaf(w1.y, h4.y,
                      fmaf(w1.z, h4.z, fmaf(w1.w, h4.w, acc1[r]))));
        }
    }

    float b0 = __ldg(agg_b + lane);
    float b1 = __ldg(agg_b + lane + 32);
#pragma unroll
    for (int r = 0; r < RPW; r++) {
        int row = rowbase + r;
        if (row < n_rows) {
            float v0 = acc0[r] + b0;
            float v1 = acc1[r] + b1;
            float* o = out + (size_t)row * D;
            o[lane]      = v0 > 0.f ? v0 : expm1f(v0);
            o[32 + lane] = v1 > 0.f ? v1 : expm1f(v1);
        }
    }
}

// ---------------------------------------------------------------------------
// Inputs (metadata order):
//  0 cids            int32  [N]       (unused by forward)
//  1 cate_emb_w      f32    [Vc, 64]
//  2 scene_emb_w     f32    [Vs, 64]
//  3 cate_scene_pad  int32  [N, 10]
//  4 c_cate_pad      int32  [N, 16]
//  5 agg_W           f32    [64, 128]
//  6 agg_b           f32    [64]
// out: f32 [N, 64]
// ---------------------------------------------------------------------------
extern "C" void kernel_launch(void* const* d_in, const int* in_sizes, int n_in,
                              void* d_out, int out_size) {
    const float* cate_emb       = (const float*)d_in[1];
    const float* scene_emb      = (const float*)d_in[2];
    const int*   cate_scene_pad = (const int*)d_in[3];
    const int*   c_cate_pad     = (const int*)d_in[4];
    const float* agg_W          = (const float*)d_in[5];
    const float* agg_b          = (const float*)d_in[6];
    float* out = (float*)d_out;

    int n_rows  = in_sizes[4] / NGH;   // 100000
    int v_cates = in_sizes[1] / D;     // 100000

    int threadsA = 256;
    int blocksA = (n_rows * 16 + threadsA - 1) / threadsA;
    rowsum_kernel<<<blocksA, threadsA>>>(scene_emb, cate_scene_pad, agg_W,
                                         cate_emb, n_rows, v_cates);

    int blocksB = (n_rows + RPB - 1) / RPB;
    main_kernel<<<blocksB, 256>>>(c_cate_pad, agg_b, out, n_rows, v_cates);
}